// round 8
// baseline (speedup 1.0000x reference)
#include <cuda_runtime.h>

#define NNODES 100000
#define NEDGES 1000000
#define NGRAPHS 1000
#define EMBED 64
#define OUTDIM 128
#define NCONV 3
#define BN_EPS 1e-5f

#define SCAN_BLOCKS ((NNODES + 255) / 256)   // 391
#define EPAD (NEDGES + 3 * NNODES + 4)       // padded edge capacity
#define SENT (((unsigned)NNODES) << 8)       // sentinel edge: src=NNODES, ef=0

typedef unsigned long long u64;

// ---------------- scratch (no allocs allowed) ----------------
// stats MUST be 16B-aligned (float4 loads) -> placed first.
struct alignas(16) ZBuf {     // zeroed via one cudaMemsetAsync each call
    float stats[NCONV * 2 * EMBED];   // offset 0, 1536 B (mult of 16)
    int   deg[NNODES];
    int   cnt;                 // scan arrival counter
    int   done;                // scan completion flag
};
__device__ ZBuf d_Z;

__device__ float d_h[(NNODES + 1) * EMBED];  // node features + sentinel row (-1e30)
__device__ float d_t[NNODES * EMBED];        // agg + h (GEMM input)
__device__ float d_y[NNODES * EMBED];        // GEMM output (pre-BN)
__device__ int   d_rowptr[NNODES + 1];       // PADDED csr offsets (mult of 4)
__device__ int   d_cursor[NNODES];
__device__ float d_inv[NNODES];              // 1/max(true_deg,1)
__device__ int   d_aggr[512];
__device__ int   d_off[512];
__device__ unsigned d_edge[EPAD];            // packed: (src << 8) | efeat
__device__ float d_gn[NGRAPHS * EMBED];

// ---------------- f32x2 helpers ----------------
__device__ __forceinline__ u64 ffma2(u64 a, u64 b, u64 c) {
    u64 d;
    asm("fma.rn.f32x2 %0, %1, %2, %3;" : "=l"(d) : "l"(a), "l"(b), "l"(c));
    return d;
}
__device__ __forceinline__ u64 pack2(float x) {
    u64 d;
    asm("mov.b64 %0, {%1, %1};" : "=l"(d) : "f"(x));
    return d;
}

// ---------------- setup kernels ----------------
// embed (+ sentinel row) + degree count
__global__ void k_embed_count(const int* __restrict__ nfeat,
                              const float4* __restrict__ atom_embed,
                              const int* __restrict__ dst) {
    int i = blockIdx.x * 256 + threadIdx.x;
    if (i < NNODES * 16) {
        int n = i >> 4, c4 = i & 15;
        ((float4*)d_h)[i] = atom_embed[nfeat[n] * 16 + c4];
    } else if (i < NNODES * 16 + 16) {
        ((float4*)d_h)[i] = make_float4(-1e30f, -1e30f, -1e30f, -1e30f);
    }
    if (i < NEDGES) atomicAdd(&d_Z.deg[dst[i]], 1);
}

// single-kernel exclusive scan over PADDED degrees -> rowptr; also d_inv.
// 391 blocks all resident -> spin safe.
__global__ void k_scan() {
    __shared__ int s[256];
    __shared__ int s2[256];
    __shared__ int sdone;
    int t = threadIdx.x, bid = blockIdx.x;
    int i = bid * 256 + t;
    int v = (i < NNODES) ? d_Z.deg[i] : 0;
    int vp = (v + 3) & ~3;               // padded degree
    s[t] = vp;
    __syncthreads();
    #pragma unroll
    for (int off = 1; off < 256; off <<= 1) {
        int u = (t >= off) ? s[t - off] : 0;
        __syncthreads();
        s[t] += u;
        __syncthreads();
    }
    int lexcl = s[t] - vp;
    int agg = s[255];
    if (t == 0) {
        d_aggr[bid] = agg;
        __threadfence();
        int old = atomicAdd(&d_Z.cnt, 1);
        sdone = (old == SCAN_BLOCKS - 1);
    }
    __syncthreads();
    if (sdone) {
        int a0 = (2 * t < SCAN_BLOCKS) ? d_aggr[2 * t] : 0;
        int a1 = (2 * t + 1 < SCAN_BLOCKS) ? d_aggr[2 * t + 1] : 0;
        s2[t] = a0 + a1;
        __syncthreads();
        #pragma unroll
        for (int off = 1; off < 256; off <<= 1) {
            int u = (t >= off) ? s2[t - off] : 0;
            __syncthreads();
            s2[t] += u;
            __syncthreads();
        }
        int ex = s2[t] - (a0 + a1);
        d_off[2 * t] = ex;
        d_off[2 * t + 1] = ex + a0;
        if (t == 255) d_rowptr[NNODES] = s2[255];
        __threadfence();
        if (t == 0) atomicExch(&d_Z.done, 1);
    }
    if (t == 0) {
        while (atomicAdd(&d_Z.done, 0) == 0) __nanosleep(40);
    }
    __syncthreads();
    int boff = __ldcg(&d_off[bid]);
    if (i < NNODES) {
        int r = lexcl + boff;
        d_rowptr[i] = r;
        d_cursor[i] = r;
        d_inv[i] = 1.f / (float)(v > 0 ? v : 1);
    }
}

// scatter real edges (atomic cursor) + write sentinel pads (node-parallel)
__global__ void k_fill(const int* __restrict__ src,
                       const int* __restrict__ efeat,
                       const int* __restrict__ dst) {
    int e = blockIdx.x * blockDim.x + threadIdx.x;
    if (e < NEDGES) {
        int p = atomicAdd(&d_cursor[dst[e]], 1);
        d_edge[p] = ((unsigned)src[e] << 8) | (unsigned)efeat[e];
    }
    if (e < NNODES) {
        int rs = d_rowptr[e];
        int dg = d_Z.deg[e];
        int dp = (dg + 3) & ~3;
        for (int q = rs + dg; q < rs + dp; q++) d_edge[q] = SENT;
    }
}

// ---------------- per-layer kernels ----------------
// warp per node, lane covers 2 channels (float2). Degree padded to mult of 4:
// no tail, edge list 16B-aligned -> one LDG.128 fetches 4 edge words.
// t[n] = mean_e relu(bond[ef] + h[src]) + h[n]
__global__ void __launch_bounds__(256) k_msg(const float* __restrict__ bond) {
    __shared__ __align__(16) float bsh[5 * EMBED];
    int tid = threadIdx.x;
    for (int i = tid; i < 5 * EMBED; i += 256) bsh[i] = bond[i];
    __syncthreads();
    int warp = tid >> 5, lane = tid & 31;
    int node = blockIdx.x * 8 + warp;
    if (node >= NNODES) return;
    int rs = d_rowptr[node], re = d_rowptr[node + 1];
    const char* hb = (const char*)d_h + lane * 8;
    const char* bb = (const char*)bsh + lane * 8;
    float2 a0 = make_float2(0.f, 0.f), a1 = a0, a2 = a0, a3 = a0;
    for (int e = rs; e < re; e += 4) {
        uint4 p = *(const uint4*)(d_edge + e);   // 4 edges, one LDG.128
        float2 h0 = *(const float2*)(hb + (p.x & 0xFFFFFF00u));
        float2 h1 = *(const float2*)(hb + (p.y & 0xFFFFFF00u));
        float2 h2 = *(const float2*)(hb + (p.z & 0xFFFFFF00u));
        float2 h3 = *(const float2*)(hb + (p.w & 0xFFFFFF00u));
        float2 b0 = *(const float2*)(bb + ((p.x & 255u) << 8));
        float2 b1 = *(const float2*)(bb + ((p.y & 255u) << 8));
        float2 b2 = *(const float2*)(bb + ((p.z & 255u) << 8));
        float2 b3 = *(const float2*)(bb + ((p.w & 255u) << 8));
        a0.x += fmaxf(b0.x + h0.x, 0.f);  a0.y += fmaxf(b0.y + h0.y, 0.f);
        a1.x += fmaxf(b1.x + h1.x, 0.f);  a1.y += fmaxf(b1.y + h1.y, 0.f);
        a2.x += fmaxf(b2.x + h2.x, 0.f);  a2.y += fmaxf(b2.y + h2.y, 0.f);
        a3.x += fmaxf(b3.x + h3.x, 0.f);  a3.y += fmaxf(b3.y + h3.y, 0.f);
    }
    a0.x += a1.x + a2.x + a3.x;
    a0.y += a1.y + a2.y + a3.y;
    float inv = d_inv[node];
    float2 hn = ((const float2*)(d_h + (size_t)node * EMBED))[lane];
    float2 o;
    o.x = a0.x * inv + hn.x;
    o.y = a0.y * inv + hn.y;
    ((float2*)(d_t + (size_t)node * EMBED))[lane] = o;
}

// thread per node: y = t @ W + b, packed f32x2 FMA, all 64 outputs live.
__global__ void __launch_bounds__(256) k_gemm(const float* __restrict__ W,
                                              const float* __restrict__ b) {
    __shared__ ulonglong2 Ws[EMBED * 16];
    int tid = threadIdx.x;
    for (int i = tid; i < EMBED * 16; i += 256) Ws[i] = ((const ulonglong2*)W)[i];
    __syncthreads();
    int node = blockIdx.x * 256 + tid;
    if (node >= NNODES) return;
    u64 acc[32];
    const u64* bp = (const u64*)b;
    #pragma unroll
    for (int i = 0; i < 32; i++) acc[i] = bp[i];
    const float4* tp = (const float4*)(d_t + (size_t)node * EMBED);
    #pragma unroll 1
    for (int k4 = 0; k4 < 16; k4++) {
        float4 tv = tp[k4];
        #pragma unroll
        for (int j = 0; j < 4; j++) {
            float tk = (j == 0) ? tv.x : (j == 1) ? tv.y : (j == 2) ? tv.z : tv.w;
            u64 tkk = pack2(tk);
            int k = k4 * 4 + j;
            #pragma unroll
            for (int c8 = 0; c8 < 16; c8++) {
                ulonglong2 w = Ws[k * 16 + c8];
                acc[2 * c8]     = ffma2(tkk, w.x, acc[2 * c8]);
                acc[2 * c8 + 1] = ffma2(tkk, w.y, acc[2 * c8 + 1]);
            }
        }
    }
    ulonglong2* yp = (ulonglong2*)(d_y + (size_t)node * EMBED);
    #pragma unroll
    for (int i = 0; i < 16; i++)
        yp[i] = make_ulonglong2(acc[2 * i], acc[2 * i + 1]);
}

// per-channel sum / sumsq over all nodes, float4-wide
__global__ void k_stats(int layer) {
    __shared__ float4 ssum[256], ssq[256];
    int tid = threadIdx.x;
    int c4 = tid & 15, grp = tid >> 4;   // 16 row-groups x 16 float4-channels
    float4 sum = make_float4(0.f, 0.f, 0.f, 0.f), sq = sum;
    for (int row = blockIdx.x * 16 + grp; row < NNODES; row += gridDim.x * 16) {
        float4 v = ((const float4*)d_y)[row * 16 + c4];
        sum.x += v.x; sum.y += v.y; sum.z += v.z; sum.w += v.w;
        sq.x += v.x * v.x; sq.y += v.y * v.y; sq.z += v.z * v.z; sq.w += v.w * v.w;
    }
    ssum[tid] = sum; ssq[tid] = sq;
    __syncthreads();
    if (grp == 0) {
        #pragma unroll
        for (int g = 1; g < 16; g++) {
            float4 a = ssum[g * 16 + c4], q = ssq[g * 16 + c4];
            sum.x += a.x; sum.y += a.y; sum.z += a.z; sum.w += a.w;
            sq.x += q.x; sq.y += q.y; sq.z += q.z; sq.w += q.w;
        }
        float* st = d_Z.stats + layer * 128;
        atomicAdd(&st[c4 * 4 + 0], sum.x);
        atomicAdd(&st[c4 * 4 + 1], sum.y);
        atomicAdd(&st[c4 * 4 + 2], sum.z);
        atomicAdd(&st[c4 * 4 + 3], sum.w);
        atomicAdd(&st[64 + c4 * 4 + 0], sq.x);
        atomicAdd(&st[64 + c4 * 4 + 1], sq.y);
        atomicAdd(&st[64 + c4 * 4 + 2], sq.z);
        atomicAdd(&st[64 + c4 * 4 + 3], sq.w);
    }
}

// normalize + gamma/beta + optional relu + residual (h += act), float4 wide
__global__ void k_bn(int layer, const float* __restrict__ gamma,
                     const float* __restrict__ beta, int do_relu) {
    int i = blockIdx.x * blockDim.x + threadIdx.x;   // float4 index
    if (i >= NNODES * 16) return;
    int c4 = i & 15;
    const float* st = d_Z.stats + layer * 128;
    const float invN = 1.f / (float)NNODES;
    float4 s1 = ((const float4*)st)[c4];
    float4 s2 = ((const float4*)(st + 64))[c4];
    float4 g  = ((const float4*)gamma)[c4];
    float4 be = ((const float4*)beta)[c4];
    float4 y  = ((const float4*)d_y)[i];
    float4 h  = ((const float4*)d_h)[i];
    float mu, var, rs, v;
    #define BN1(X) \
        mu = s1.X * invN; var = s2.X * invN - mu * mu; \
        rs = rsqrtf(fmaxf(var, 0.f) + BN_EPS); \
        v = (y.X - mu) * rs * g.X + be.X; \
        if (do_relu) v = fmaxf(v, 0.f); \
        h.X += v;
    BN1(x) BN1(y) BN1(z) BN1(w)
    #undef BN1
    ((float4*)d_h)[i] = h;
}

// ---------------- tail kernels ----------------
__global__ void k_pool(const int* __restrict__ gids) {
    __shared__ float red[256];
    __shared__ int range[2];
    int g = blockIdx.x, tid = threadIdx.x;
    int c = tid & 63, grp = tid >> 6;
    if (tid < 2) {
        int target = g + tid;
        int lo = 0, hi = NNODES;
        while (lo < hi) { int m = (lo + hi) >> 1; if (gids[m] < target) lo = m + 1; else hi = m; }
        range[tid] = lo;
    }
    __syncthreads();
    int start = range[0], end = range[1];
    float acc = 0.f;
    for (int n = start + grp; n < end; n += 4)
        acc += d_h[(size_t)n * EMBED + c];
    red[tid] = acc;
    __syncthreads();
    if (grp == 0) {
        float s = red[c] + red[64 + c] + red[128 + c] + red[192 + c];
        int cntg = end - start;
        d_gn[g * EMBED + c] = s / (float)(cntg > 0 ? cntg : 1);
    }
}

__global__ void k_pred(const float* __restrict__ W, const float* __restrict__ b,
                       float* __restrict__ out) {
    __shared__ float gs[EMBED];
    int g = blockIdx.x, o = threadIdx.x;
    if (o < EMBED) gs[o] = d_gn[g * EMBED + o];
    __syncthreads();
    float acc = b[o];
    #pragma unroll
    for (int k = 0; k < EMBED; k++) acc += gs[k] * W[k * OUTDIM + o];
    out[g * OUTDIM + o] = acc;
}

// ---------------- launch ----------------
extern "C" void kernel_launch(void* const* d_in, const int* in_sizes, int n_in,
                              void* d_out, int out_size) {
    const int*   nfeat      = (const int*)d_in[0];
    const int*   efeat      = (const int*)d_in[1];
    const int*   src        = (const int*)d_in[2];
    const int*   dst        = (const int*)d_in[3];
    const int*   gids       = (const int*)d_in[4];
    const float* atom_embed = (const float*)d_in[5];
    const float* bond_embed = (const float*)d_in[6];
    const float* conv_W     = (const float*)d_in[7];
    const float* conv_b     = (const float*)d_in[8];
    const float* bn_gamma   = (const float*)d_in[9];
    const float* bn_beta    = (const float*)d_in[10];
    const float* pred_W     = (const float*)d_in[11];
    const float* pred_b     = (const float*)d_in[12];
    float* out = (float*)d_out;

    void* zp = nullptr;
    cudaGetSymbolAddress(&zp, d_Z);
    cudaMemsetAsync(zp, 0, sizeof(ZBuf), 0);

    k_embed_count<<<(NNODES * 16 + 16 + 255) / 256, 256>>>(nfeat, (const float4*)atom_embed, dst);
    k_scan<<<SCAN_BLOCKS, 256>>>();
    k_fill<<<(NEDGES + 255) / 256, 256>>>(src, efeat, dst);

    for (int i = 0; i < NCONV; i++) {
        k_msg<<<(NNODES + 7) / 8, 256>>>(bond_embed + i * 5 * EMBED);
        k_gemm<<<(NNODES + 255) / 256, 256>>>(conv_W + i * EMBED * EMBED,
                                              conv_b + i * EMBED);
        k_stats<<<256, 256>>>(i);
        k_bn<<<(NNODES * 16 + 255) / 256, 256>>>(i, bn_gamma + i * EMBED,
                                                 bn_beta + i * EMBED,
                                                 (i < NCONV - 1) ? 1 : 0);
    }

    k_pool<<<NGRAPHS, 256>>>(gids);
    k_pred<<<NGRAPHS, OUTDIM>>>(pred_W, pred_b, out);
}

// round 9
// speedup vs baseline: 1.4615x; 1.4615x over previous
#include <cuda_runtime.h>

#define NNODES 100000
#define NEDGES 1000000
#define NGRAPHS 1000
#define EMBED 64
#define OUTDIM 128
#define NCONV 3
#define BN_EPS 1e-5f

#define SCAN_BLOCKS ((NNODES + 255) / 256)   // 391

typedef unsigned long long u64;

// ---------------- scratch (no allocs allowed) ----------------
// stats MUST be 16B-aligned (float4 loads) -> placed first.
struct alignas(16) ZBuf {     // zeroed via one cudaMemsetAsync each call
    float stats[NCONV * 2 * EMBED];   // offset 0, 1536 B (mult of 16)
    int   deg[NNODES];
    int   cnt;                 // scan arrival counter
    int   done;                // scan completion flag
};
__device__ ZBuf d_Z;

__device__ float d_h[NNODES * EMBED];      // node features
__device__ float d_t[NNODES * EMBED];      // agg + h (GEMM input)
__device__ float d_y[NNODES * EMBED];      // GEMM output (pre-BN)
__device__ int   d_rowptr[NNODES + 1];
__device__ int   d_cursor[NNODES];
__device__ float d_inv[NNODES];            // 1/max(deg,1)
__device__ int   d_aggr[512];
__device__ int   d_off[512];
__device__ unsigned d_edge[NEDGES];        // packed: (src << 8) | efeat
__device__ float d_gn[NGRAPHS * EMBED];

// ---------------- f32x2 helpers ----------------
__device__ __forceinline__ u64 ffma2(u64 a, u64 b, u64 c) {
    u64 d;
    asm("fma.rn.f32x2 %0, %1, %2, %3;" : "=l"(d) : "l"(a), "l"(b), "l"(c));
    return d;
}
__device__ __forceinline__ u64 pack2(float x) {
    u64 d;
    asm("mov.b64 %0, {%1, %1};" : "=l"(d) : "f"(x));
    return d;
}

// ---------------- setup kernels ----------------
__global__ void k_embed_count(const int* __restrict__ nfeat,
                              const float4* __restrict__ atom_embed,
                              const int* __restrict__ dst) {
    int i = blockIdx.x * 256 + threadIdx.x;
    if (i < NNODES * 16) {
        int n = i >> 4, c4 = i & 15;
        ((float4*)d_h)[i] = atom_embed[nfeat[n] * 16 + c4];
    }
    if (i < NEDGES) atomicAdd(&d_Z.deg[dst[i]], 1);
}

// single-kernel exclusive scan: block-local scan, last-arriving block computes
// the 391 block offsets, everyone else spins. 391 blocks all resident -> safe.
__global__ void k_scan() {
    __shared__ int s[256];
    __shared__ int s2[256];
    __shared__ int sdone;
    int t = threadIdx.x, bid = blockIdx.x;
    int i = bid * 256 + t;
    int v = (i < NNODES) ? d_Z.deg[i] : 0;
    s[t] = v;
    __syncthreads();
    #pragma unroll
    for (int off = 1; off < 256; off <<= 1) {
        int u = (t >= off) ? s[t - off] : 0;
        __syncthreads();
        s[t] += u;
        __syncthreads();
    }
    int lexcl = s[t] - v;
    int agg = s[255];
    if (t == 0) {
        d_aggr[bid] = agg;
        __threadfence();
        int old = atomicAdd(&d_Z.cnt, 1);
        sdone = (old == SCAN_BLOCKS - 1);
    }
    __syncthreads();
    if (sdone) {
        int a0 = (2 * t < SCAN_BLOCKS) ? d_aggr[2 * t] : 0;
        int a1 = (2 * t + 1 < SCAN_BLOCKS) ? d_aggr[2 * t + 1] : 0;
        s2[t] = a0 + a1;
        __syncthreads();
        #pragma unroll
        for (int off = 1; off < 256; off <<= 1) {
            int u = (t >= off) ? s2[t - off] : 0;
            __syncthreads();
            s2[t] += u;
            __syncthreads();
        }
        int ex = s2[t] - (a0 + a1);
        d_off[2 * t] = ex;
        d_off[2 * t + 1] = ex + a0;
        if (t == 255) d_rowptr[NNODES] = s2[255];
        __threadfence();
        if (t == 0) atomicExch(&d_Z.done, 1);
    }
    if (t == 0) {
        while (atomicAdd(&d_Z.done, 0) == 0) __nanosleep(40);
    }
    __syncthreads();
    int boff = __ldcg(&d_off[bid]);
    if (i < NNODES) {
        int r = lexcl + boff;
        d_rowptr[i] = r;
        d_cursor[i] = r;
        d_inv[i] = 1.f / (float)(v > 0 ? v : 1);
    }
}

__global__ void k_fill(const int* __restrict__ src,
                       const int* __restrict__ efeat,
                       const int* __restrict__ dst) {
    int e = blockIdx.x * blockDim.x + threadIdx.x;
    if (e >= NEDGES) return;
    int p = atomicAdd(&d_cursor[dst[e]], 1);
    d_edge[p] = ((unsigned)src[e] << 8) | (unsigned)efeat[e];
}

// ---------------- per-layer kernels ----------------
// warp per node, lane covers 2 channels (float2). 4x-unrolled edge loop
// (R4 structure) with byte-offset packed edges: gather addr = base + (p & ~255),
// bond addr = base + ((p & 255) << 8).
// t[n] = mean_e relu(bond[ef] + h[src]) + h[n]
__global__ void __launch_bounds__(256) k_msg(const float* __restrict__ bond) {
    __shared__ __align__(16) float bsh[5 * EMBED];
    int tid = threadIdx.x;
    for (int i = tid; i < 5 * EMBED; i += 256) bsh[i] = bond[i];
    __syncthreads();
    int warp = tid >> 5, lane = tid & 31;
    int node = blockIdx.x * 8 + warp;
    if (node >= NNODES) return;
    int rs = d_rowptr[node], re = d_rowptr[node + 1];
    const char* hb = (const char*)d_h + lane * 8;
    const char* bb = (const char*)bsh + lane * 8;
    float2 a0 = make_float2(0.f, 0.f), a1 = a0, a2 = a0, a3 = a0;
    int e = rs;
    for (; e + 3 < re; e += 4) {
        unsigned p0 = d_edge[e],     p1 = d_edge[e + 1];
        unsigned p2 = d_edge[e + 2], p3 = d_edge[e + 3];
        float2 h0 = *(const float2*)(hb + (p0 & 0xFFFFFF00u));
        float2 h1 = *(const float2*)(hb + (p1 & 0xFFFFFF00u));
        float2 h2 = *(const float2*)(hb + (p2 & 0xFFFFFF00u));
        float2 h3 = *(const float2*)(hb + (p3 & 0xFFFFFF00u));
        float2 b0 = *(const float2*)(bb + ((p0 & 255u) << 8));
        float2 b1 = *(const float2*)(bb + ((p1 & 255u) << 8));
        float2 b2 = *(const float2*)(bb + ((p2 & 255u) << 8));
        float2 b3 = *(const float2*)(bb + ((p3 & 255u) << 8));
        a0.x += fmaxf(b0.x + h0.x, 0.f);  a0.y += fmaxf(b0.y + h0.y, 0.f);
        a1.x += fmaxf(b1.x + h1.x, 0.f);  a1.y += fmaxf(b1.y + h1.y, 0.f);
        a2.x += fmaxf(b2.x + h2.x, 0.f);  a2.y += fmaxf(b2.y + h2.y, 0.f);
        a3.x += fmaxf(b3.x + h3.x, 0.f);  a3.y += fmaxf(b3.y + h3.y, 0.f);
    }
    for (; e < re; e++) {
        unsigned p0 = d_edge[e];
        float2 h0 = *(const float2*)(hb + (p0 & 0xFFFFFF00u));
        float2 b0 = *(const float2*)(bb + ((p0 & 255u) << 8));
        a0.x += fmaxf(b0.x + h0.x, 0.f);  a0.y += fmaxf(b0.y + h0.y, 0.f);
    }
    a0.x += a1.x + a2.x + a3.x;
    a0.y += a1.y + a2.y + a3.y;
    float inv = d_inv[node];
    float2 hn = ((const float2*)(d_h + (size_t)node * EMBED))[lane];
    float2 o;
    o.x = a0.x * inv + hn.x;
    o.y = a0.y * inv + hn.y;
    ((float2*)(d_t + (size_t)node * EMBED))[lane] = o;
}

// thread per node: y = t @ W + b, packed f32x2 FMA, all 64 outputs live.
__global__ void __launch_bounds__(256) k_gemm(const float* __restrict__ W,
                                              const float* __restrict__ b) {
    __shared__ ulonglong2 Ws[EMBED * 16];
    int tid = threadIdx.x;
    for (int i = tid; i < EMBED * 16; i += 256) Ws[i] = ((const ulonglong2*)W)[i];
    __syncthreads();
    int node = blockIdx.x * 256 + tid;
    if (node >= NNODES) return;
    u64 acc[32];
    const u64* bp = (const u64*)b;
    #pragma unroll
    for (int i = 0; i < 32; i++) acc[i] = bp[i];
    const float4* tp = (const float4*)(d_t + (size_t)node * EMBED);
    #pragma unroll 1
    for (int k4 = 0; k4 < 16; k4++) {
        float4 tv = tp[k4];
        #pragma unroll
        for (int j = 0; j < 4; j++) {
            float tk = (j == 0) ? tv.x : (j == 1) ? tv.y : (j == 2) ? tv.z : tv.w;
            u64 tkk = pack2(tk);
            int k = k4 * 4 + j;
            #pragma unroll
            for (int c8 = 0; c8 < 16; c8++) {
                ulonglong2 w = Ws[k * 16 + c8];
                acc[2 * c8]     = ffma2(tkk, w.x, acc[2 * c8]);
                acc[2 * c8 + 1] = ffma2(tkk, w.y, acc[2 * c8 + 1]);
            }
        }
    }
    ulonglong2* yp = (ulonglong2*)(d_y + (size_t)node * EMBED);
    #pragma unroll
    for (int i = 0; i < 16; i++)
        yp[i] = make_ulonglong2(acc[2 * i], acc[2 * i + 1]);
}

// per-channel sum / sumsq over all nodes, float4-wide
__global__ void k_stats(int layer) {
    __shared__ float4 ssum[256], ssq[256];
    int tid = threadIdx.x;
    int c4 = tid & 15, grp = tid >> 4;   // 16 row-groups x 16 float4-channels
    float4 sum = make_float4(0.f, 0.f, 0.f, 0.f), sq = sum;
    for (int row = blockIdx.x * 16 + grp; row < NNODES; row += gridDim.x * 16) {
        float4 v = ((const float4*)d_y)[row * 16 + c4];
        sum.x += v.x; sum.y += v.y; sum.z += v.z; sum.w += v.w;
        sq.x += v.x * v.x; sq.y += v.y * v.y; sq.z += v.z * v.z; sq.w += v.w * v.w;
    }
    ssum[tid] = sum; ssq[tid] = sq;
    __syncthreads();
    if (grp == 0) {
        #pragma unroll
        for (int g = 1; g < 16; g++) {
            float4 a = ssum[g * 16 + c4], q = ssq[g * 16 + c4];
            sum.x += a.x; sum.y += a.y; sum.z += a.z; sum.w += a.w;
            sq.x += q.x; sq.y += q.y; sq.z += q.z; sq.w += q.w;
        }
        float* st = d_Z.stats + layer * 128;
        atomicAdd(&st[c4 * 4 + 0], sum.x);
        atomicAdd(&st[c4 * 4 + 1], sum.y);
        atomicAdd(&st[c4 * 4 + 2], sum.z);
        atomicAdd(&st[c4 * 4 + 3], sum.w);
        atomicAdd(&st[64 + c4 * 4 + 0], sq.x);
        atomicAdd(&st[64 + c4 * 4 + 1], sq.y);
        atomicAdd(&st[64 + c4 * 4 + 2], sq.z);
        atomicAdd(&st[64 + c4 * 4 + 3], sq.w);
    }
}

// normalize + gamma/beta + optional relu + residual (h += act), float4 wide
__global__ void k_bn(int layer, const float* __restrict__ gamma,
                     const float* __restrict__ beta, int do_relu) {
    int i = blockIdx.x * blockDim.x + threadIdx.x;   // float4 index
    if (i >= NNODES * 16) return;
    int c4 = i & 15;
    const float* st = d_Z.stats + layer * 128;
    const float invN = 1.f / (float)NNODES;
    float4 s1 = ((const float4*)st)[c4];
    float4 s2 = ((const float4*)(st + 64))[c4];
    float4 g  = ((const float4*)gamma)[c4];
    float4 be = ((const float4*)beta)[c4];
    float4 y  = ((const float4*)d_y)[i];
    float4 h  = ((const float4*)d_h)[i];
    float mu, var, rs, v;
    #define BN1(X) \
        mu = s1.X * invN; var = s2.X * invN - mu * mu; \
        rs = rsqrtf(fmaxf(var, 0.f) + BN_EPS); \
        v = (y.X - mu) * rs * g.X + be.X; \
        if (do_relu) v = fmaxf(v, 0.f); \
        h.X += v;
    BN1(x) BN1(y) BN1(z) BN1(w)
    #undef BN1
    ((float4*)d_h)[i] = h;
}

// ---------------- tail kernels ----------------
__global__ void k_pool(const int* __restrict__ gids) {
    __shared__ float red[256];
    __shared__ int range[2];
    int g = blockIdx.x, tid = threadIdx.x;
    int c = tid & 63, grp = tid >> 6;
    if (tid < 2) {
        int target = g + tid;
        int lo = 0, hi = NNODES;
        while (lo < hi) { int m = (lo + hi) >> 1; if (gids[m] < target) lo = m + 1; else hi = m; }
        range[tid] = lo;
    }
    __syncthreads();
    int start = range[0], end = range[1];
    float acc = 0.f;
    for (int n = start + grp; n < end; n += 4)
        acc += d_h[(size_t)n * EMBED + c];
    red[tid] = acc;
    __syncthreads();
    if (grp == 0) {
        float s = red[c] + red[64 + c] + red[128 + c] + red[192 + c];
        int cntg = end - start;
        d_gn[g * EMBED + c] = s / (float)(cntg > 0 ? cntg : 1);
    }
}

__global__ void k_pred(const float* __restrict__ W, const float* __restrict__ b,
                       float* __restrict__ out) {
    __shared__ float gs[EMBED];
    int g = blockIdx.x, o = threadIdx.x;
    if (o < EMBED) gs[o] = d_gn[g * EMBED + o];
    __syncthreads();
    float acc = b[o];
    #pragma unroll
    for (int k = 0; k < EMBED; k++) acc += gs[k] * W[k * OUTDIM + o];
    out[g * OUTDIM + o] = acc;
}

// ---------------- launch ----------------
extern "C" void kernel_launch(void* const* d_in, const int* in_sizes, int n_in,
                              void* d_out, int out_size) {
    const int*   nfeat      = (const int*)d_in[0];
    const int*   efeat      = (const int*)d_in[1];
    const int*   src        = (const int*)d_in[2];
    const int*   dst        = (const int*)d_in[3];
    const int*   gids       = (const int*)d_in[4];
    const float* atom_embed = (const float*)d_in[5];
    const float* bond_embed = (const float*)d_in[6];
    const float* conv_W     = (const float*)d_in[7];
    const float* conv_b     = (const float*)d_in[8];
    const float* bn_gamma   = (const float*)d_in[9];
    const float* bn_beta    = (const float*)d_in[10];
    const float* pred_W     = (const float*)d_in[11];
    const float* pred_b     = (const float*)d_in[12];
    float* out = (float*)d_out;

    void* zp = nullptr;
    cudaGetSymbolAddress(&zp, d_Z);
    cudaMemsetAsync(zp, 0, sizeof(ZBuf), 0);

    k_embed_count<<<(NNODES * 16 + 255) / 256, 256>>>(nfeat, (const float4*)atom_embed, dst);
    k_scan<<<SCAN_BLOCKS, 256>>>();
    k_fill<<<(NEDGES + 255) / 256, 256>>>(src, efeat, dst);

    for (int i = 0; i < NCONV; i++) {
        k_msg<<<(NNODES + 7) / 8, 256>>>(bond_embed + i * 5 * EMBED);
        k_gemm<<<(NNODES + 255) / 256, 256>>>(conv_W + i * EMBED * EMBED,
                                              conv_b + i * EMBED);
        k_stats<<<256, 256>>>(i);
        k_bn<<<(NNODES * 16 + 255) / 256, 256>>>(i, bn_gamma + i * EMBED,
                                                 bn_beta + i * EMBED,
                                                 (i < NCONV - 1) ? 1 : 0);
    }

    k_pool<<<NGRAPHS, 256>>>(gids);
    k_pred<<<NGRAPHS, OUTDIM>>>(pred_W, pred_b, out);
}

// round 10
// speedup vs baseline: 1.5508x; 1.0611x over previous
#include <cuda_runtime.h>

#define NNODES 100000
#define NEDGES 1000000
#define NGRAPHS 1000
#define EMBED 64
#define OUTDIM 128
#define NCONV 3
#define BN_EPS 1e-5f

#define SCAN_BLOCKS ((NNODES + 255) / 256)   // 391

typedef unsigned long long u64;

// ---------------- scratch (no allocs allowed) ----------------
// stats MUST be 16B-aligned (float4 loads) -> placed first.
struct alignas(16) ZBuf {     // zeroed via one cudaMemsetAsync each call
    float stats[NCONV * 2 * EMBED];   // offset 0, 1536 B (mult of 16)
    int   deg[NNODES];
    int   cnt;                 // scan arrival counter
    int   done;                // scan completion flag
};
__device__ ZBuf d_Z;

__device__ float d_h[NNODES * EMBED];      // node features
__device__ float d_t[NNODES * EMBED];      // agg + h (GEMM input)
__device__ float d_y[NNODES * EMBED];      // GEMM output (pre-BN)
__device__ int   d_rowptr[NNODES + 1];
__device__ int   d_cursor[NNODES];
__device__ float d_inv[NNODES];            // 1/max(deg,1)
__device__ int   d_aggr[512];
__device__ int   d_off[512];
__device__ unsigned d_edge[NEDGES];        // packed: (src << 8) | efeat
__device__ float d_gn[NGRAPHS * EMBED];

// ---------------- f32x2 helpers ----------------
__device__ __forceinline__ u64 ffma2(u64 a, u64 b, u64 c) {
    u64 d;
    asm("fma.rn.f32x2 %0, %1, %2, %3;" : "=l"(d) : "l"(a), "l"(b), "l"(c));
    return d;
}
__device__ __forceinline__ u64 pack2(float x) {
    u64 d;
    asm("mov.b64 %0, {%1, %1};" : "=l"(d) : "f"(x));
    return d;
}

// ---------------- setup kernels ----------------
__global__ void k_embed_count(const int* __restrict__ nfeat,
                              const float4* __restrict__ atom_embed,
                              const int* __restrict__ dst) {
    int i = blockIdx.x * 256 + threadIdx.x;
    if (i < NNODES * 16) {
        int n = i >> 4, c4 = i & 15;
        ((float4*)d_h)[i] = atom_embed[nfeat[n] * 16 + c4];
    }
    if (i < NEDGES) atomicAdd(&d_Z.deg[dst[i]], 1);
}

// single-kernel exclusive scan: block-local scan, last-arriving block computes
// the 391 block offsets, everyone else spins. 391 blocks all resident -> safe.
__global__ void k_scan() {
    __shared__ int s[256];
    __shared__ int s2[256];
    __shared__ int sdone;
    int t = threadIdx.x, bid = blockIdx.x;
    int i = bid * 256 + t;
    int v = (i < NNODES) ? d_Z.deg[i] : 0;
    s[t] = v;
    __syncthreads();
    #pragma unroll
    for (int off = 1; off < 256; off <<= 1) {
        int u = (t >= off) ? s[t - off] : 0;
        __syncthreads();
        s[t] += u;
        __syncthreads();
    }
    int lexcl = s[t] - v;
    int agg = s[255];
    if (t == 0) {
        d_aggr[bid] = agg;
        __threadfence();
        int old = atomicAdd(&d_Z.cnt, 1);
        sdone = (old == SCAN_BLOCKS - 1);
    }
    __syncthreads();
    if (sdone) {
        int a0 = (2 * t < SCAN_BLOCKS) ? d_aggr[2 * t] : 0;
        int a1 = (2 * t + 1 < SCAN_BLOCKS) ? d_aggr[2 * t + 1] : 0;
        s2[t] = a0 + a1;
        __syncthreads();
        #pragma unroll
        for (int off = 1; off < 256; off <<= 1) {
            int u = (t >= off) ? s2[t - off] : 0;
            __syncthreads();
            s2[t] += u;
            __syncthreads();
        }
        int ex = s2[t] - (a0 + a1);
        d_off[2 * t] = ex;
        d_off[2 * t + 1] = ex + a0;
        if (t == 255) d_rowptr[NNODES] = s2[255];
        __threadfence();
        if (t == 0) atomicExch(&d_Z.done, 1);
    }
    if (t == 0) {
        while (atomicAdd(&d_Z.done, 0) == 0) __nanosleep(40);
    }
    __syncthreads();
    int boff = __ldcg(&d_off[bid]);
    if (i < NNODES) {
        int r = lexcl + boff;
        d_rowptr[i] = r;
        d_cursor[i] = r;
        d_inv[i] = 1.f / (float)(v > 0 ? v : 1);
    }
}

__global__ void k_fill(const int* __restrict__ src,
                       const int* __restrict__ efeat,
                       const int* __restrict__ dst) {
    int e = blockIdx.x * blockDim.x + threadIdx.x;
    if (e >= NEDGES) return;
    int p = atomicAdd(&d_cursor[dst[e]], 1);
    d_edge[p] = ((unsigned)src[e] << 8) | (unsigned)efeat[e];
}

// ---------------- per-layer kernels ----------------
// warp per node, lane covers 2 channels (float2). 4x-unrolled edge loop with
// byte-offset packed edges. __launch_bounds__(256, 8) pins regs to 32 so all
// 8 blocks fit per SM (R4's measured occupancy sweet spot).
// t[n] = mean_e relu(bond[ef] + h[src]) + h[n]
__global__ void __launch_bounds__(256, 8) k_msg(const float* __restrict__ bond) {
    __shared__ __align__(16) float bsh[5 * EMBED];
    int tid = threadIdx.x;
    for (int i = tid; i < 5 * EMBED; i += 256) bsh[i] = bond[i];
    __syncthreads();
    int warp = tid >> 5, lane = tid & 31;
    int node = blockIdx.x * 8 + warp;
    if (node >= NNODES) return;
    int rs = d_rowptr[node], re = d_rowptr[node + 1];
    const char* hb = (const char*)d_h + lane * 8;
    const char* bb = (const char*)bsh + lane * 8;
    float2 a0 = make_float2(0.f, 0.f), a1 = a0, a2 = a0, a3 = a0;
    int e = rs;
    for (; e + 3 < re; e += 4) {
        unsigned p0 = d_edge[e],     p1 = d_edge[e + 1];
        unsigned p2 = d_edge[e + 2], p3 = d_edge[e + 3];
        float2 h0 = *(const float2*)(hb + (p0 & 0xFFFFFF00u));
        float2 h1 = *(const float2*)(hb + (p1 & 0xFFFFFF00u));
        float2 h2 = *(const float2*)(hb + (p2 & 0xFFFFFF00u));
        float2 h3 = *(const float2*)(hb + (p3 & 0xFFFFFF00u));
        float2 b0 = *(const float2*)(bb + ((p0 & 255u) << 8));
        float2 b1 = *(const float2*)(bb + ((p1 & 255u) << 8));
        float2 b2 = *(const float2*)(bb + ((p2 & 255u) << 8));
        float2 b3 = *(const float2*)(bb + ((p3 & 255u) << 8));
        a0.x += fmaxf(b0.x + h0.x, 0.f);  a0.y += fmaxf(b0.y + h0.y, 0.f);
        a1.x += fmaxf(b1.x + h1.x, 0.f);  a1.y += fmaxf(b1.y + h1.y, 0.f);
        a2.x += fmaxf(b2.x + h2.x, 0.f);  a2.y += fmaxf(b2.y + h2.y, 0.f);
        a3.x += fmaxf(b3.x + h3.x, 0.f);  a3.y += fmaxf(b3.y + h3.y, 0.f);
    }
    for (; e < re; e++) {
        unsigned p0 = d_edge[e];
        float2 h0 = *(const float2*)(hb + (p0 & 0xFFFFFF00u));
        float2 b0 = *(const float2*)(bb + ((p0 & 255u) << 8));
        a0.x += fmaxf(b0.x + h0.x, 0.f);  a0.y += fmaxf(b0.y + h0.y, 0.f);
    }
    a0.x += a1.x + a2.x + a3.x;
    a0.y += a1.y + a2.y + a3.y;
    float inv = d_inv[node];
    float2 hn = ((const float2*)(d_h + (size_t)node * EMBED))[lane];
    float2 o;
    o.x = a0.x * inv + hn.x;
    o.y = a0.y * inv + hn.y;
    ((float2*)(d_t + (size_t)node * EMBED))[lane] = o;
}

// thread per node: y = t @ W + b, packed f32x2 FMA, all 64 outputs live.
__global__ void __launch_bounds__(256) k_gemm(const float* __restrict__ W,
                                              const float* __restrict__ b) {
    __shared__ ulonglong2 Ws[EMBED * 16];
    int tid = threadIdx.x;
    for (int i = tid; i < EMBED * 16; i += 256) Ws[i] = ((const ulonglong2*)W)[i];
    __syncthreads();
    int node = blockIdx.x * 256 + tid;
    if (node >= NNODES) return;
    u64 acc[32];
    const u64* bp = (const u64*)b;
    #pragma unroll
    for (int i = 0; i < 32; i++) acc[i] = bp[i];
    const float4* tp = (const float4*)(d_t + (size_t)node * EMBED);
    #pragma unroll 1
    for (int k4 = 0; k4 < 16; k4++) {
        float4 tv = tp[k4];
        #pragma unroll
        for (int j = 0; j < 4; j++) {
            float tk = (j == 0) ? tv.x : (j == 1) ? tv.y : (j == 2) ? tv.z : tv.w;
            u64 tkk = pack2(tk);
            int k = k4 * 4 + j;
            #pragma unroll
            for (int c8 = 0; c8 < 16; c8++) {
                ulonglong2 w = Ws[k * 16 + c8];
                acc[2 * c8]     = ffma2(tkk, w.x, acc[2 * c8]);
                acc[2 * c8 + 1] = ffma2(tkk, w.y, acc[2 * c8 + 1]);
            }
        }
    }
    ulonglong2* yp = (ulonglong2*)(d_y + (size_t)node * EMBED);
    #pragma unroll
    for (int i = 0; i < 16; i++)
        yp[i] = make_ulonglong2(acc[2 * i], acc[2 * i + 1]);
}

// per-channel sum / sumsq over all nodes, float4-wide
__global__ void k_stats(int layer) {
    __shared__ float4 ssum[256], ssq[256];
    int tid = threadIdx.x;
    int c4 = tid & 15, grp = tid >> 4;   // 16 row-groups x 16 float4-channels
    float4 sum = make_float4(0.f, 0.f, 0.f, 0.f), sq = sum;
    for (int row = blockIdx.x * 16 + grp; row < NNODES; row += gridDim.x * 16) {
        float4 v = ((const float4*)d_y)[row * 16 + c4];
        sum.x += v.x; sum.y += v.y; sum.z += v.z; sum.w += v.w;
        sq.x += v.x * v.x; sq.y += v.y * v.y; sq.z += v.z * v.z; sq.w += v.w * v.w;
    }
    ssum[tid] = sum; ssq[tid] = sq;
    __syncthreads();
    if (grp == 0) {
        #pragma unroll
        for (int g = 1; g < 16; g++) {
            float4 a = ssum[g * 16 + c4], q = ssq[g * 16 + c4];
            sum.x += a.x; sum.y += a.y; sum.z += a.z; sum.w += a.w;
            sq.x += q.x; sq.y += q.y; sq.z += q.z; sq.w += q.w;
        }
        float* st = d_Z.stats + layer * 128;
        atomicAdd(&st[c4 * 4 + 0], sum.x);
        atomicAdd(&st[c4 * 4 + 1], sum.y);
        atomicAdd(&st[c4 * 4 + 2], sum.z);
        atomicAdd(&st[c4 * 4 + 3], sum.w);
        atomicAdd(&st[64 + c4 * 4 + 0], sq.x);
        atomicAdd(&st[64 + c4 * 4 + 1], sq.y);
        atomicAdd(&st[64 + c4 * 4 + 2], sq.z);
        atomicAdd(&st[64 + c4 * 4 + 3], sq.w);
    }
}

// normalize + gamma/beta + optional relu + residual (h += act), float4 wide
__global__ void k_bn(int layer, const float* __restrict__ gamma,
                     const float* __restrict__ beta, int do_relu) {
    int i = blockIdx.x * blockDim.x + threadIdx.x;   // float4 index
    if (i >= NNODES * 16) return;
    int c4 = i & 15;
    const float* st = d_Z.stats + layer * 128;
    const float invN = 1.f / (float)NNODES;
    float4 s1 = ((const float4*)st)[c4];
    float4 s2 = ((const float4*)(st + 64))[c4];
    float4 g  = ((const float4*)gamma)[c4];
    float4 be = ((const float4*)beta)[c4];
    float4 y  = ((const float4*)d_y)[i];
    float4 h  = ((const float4*)d_h)[i];
    float mu, var, rs, v;
    #define BN1(X) \
        mu = s1.X * invN; var = s2.X * invN - mu * mu; \
        rs = rsqrtf(fmaxf(var, 0.f) + BN_EPS); \
        v = (y.X - mu) * rs * g.X + be.X; \
        if (do_relu) v = fmaxf(v, 0.f); \
        h.X += v;
    BN1(x) BN1(y) BN1(z) BN1(w)
    #undef BN1
    ((float4*)d_h)[i] = h;
}

// ---------------- tail kernels ----------------
__global__ void k_pool(const int* __restrict__ gids) {
    __shared__ float red[256];
    __shared__ int range[2];
    int g = blockIdx.x, tid = threadIdx.x;
    int c = tid & 63, grp = tid >> 6;
    if (tid < 2) {
        int target = g + tid;
        int lo = 0, hi = NNODES;
        while (lo < hi) { int m = (lo + hi) >> 1; if (gids[m] < target) lo = m + 1; else hi = m; }
        range[tid] = lo;
    }
    __syncthreads();
    int start = range[0], end = range[1];
    float acc = 0.f;
    for (int n = start + grp; n < end; n += 4)
        acc += d_h[(size_t)n * EMBED + c];
    red[tid] = acc;
    __syncthreads();
    if (grp == 0) {
        float s = red[c] + red[64 + c] + red[128 + c] + red[192 + c];
        int cntg = end - start;
        d_gn[g * EMBED + c] = s / (float)(cntg > 0 ? cntg : 1);
    }
}

__global__ void k_pred(const float* __restrict__ W, const float* __restrict__ b,
                       float* __restrict__ out) {
    __shared__ float gs[EMBED];
    int g = blockIdx.x, o = threadIdx.x;
    if (o < EMBED) gs[o] = d_gn[g * EMBED + o];
    __syncthreads();
    float acc = b[o];
    #pragma unroll
    for (int k = 0; k < EMBED; k++) acc += gs[k] * W[k * OUTDIM + o];
    out[g * OUTDIM + o] = acc;
}

// ---------------- launch ----------------
extern "C" void kernel_launch(void* const* d_in, const int* in_sizes, int n_in,
                              void* d_out, int out_size) {
    const int*   nfeat      = (const int*)d_in[0];
    const int*   efeat      = (const int*)d_in[1];
    const int*   src        = (const int*)d_in[2];
    const int*   dst        = (const int*)d_in[3];
    const int*   gids       = (const int*)d_in[4];
    const float* atom_embed = (const float*)d_in[5];
    const float* bond_embed = (const float*)d_in[6];
    const float* conv_W     = (const float*)d_in[7];
    const float* conv_b     = (const float*)d_in[8];
    const float* bn_gamma   = (const float*)d_in[9];
    const float* bn_beta    = (const float*)d_in[10];
    const float* pred_W     = (const float*)d_in[11];
    const float* pred_b     = (const float*)d_in[12];
    float* out = (float*)d_out;

    void* zp = nullptr;
    cudaGetSymbolAddress(&zp, d_Z);
    cudaMemsetAsync(zp, 0, sizeof(ZBuf), 0);

    k_embed_count<<<(NNODES * 16 + 255) / 256, 256>>>(nfeat, (const float4*)atom_embed, dst);
    k_scan<<<SCAN_BLOCKS, 256>>>();
    k_fill<<<(NEDGES + 255) / 256, 256>>>(src, efeat, dst);

    for (int i = 0; i < NCONV; i++) {
        k_msg<<<(NNODES + 7) / 8, 256>>>(bond_embed + i * 5 * EMBED);
        k_gemm<<<(NNODES + 255) / 256, 256>>>(conv_W + i * EMBED * EMBED,
                                              conv_b + i * EMBED);
        k_stats<<<256, 256>>>(i);
        k_bn<<<(NNODES * 16 + 255) / 256, 256>>>(i, bn_gamma + i * EMBED,
                                                 bn_beta + i * EMBED,
                                                 (i < NCONV - 1) ? 1 : 0);
    }

    k_pool<<<NGRAPHS, 256>>>(gids);
    k_pred<<<NGRAPHS, OUTDIM>>>(pred_W, pred_b, out);
}

// round 11
// speedup vs baseline: 1.5982x; 1.0306x over previous
#include <cuda_runtime.h>

#define NNODES 100000
#define NEDGES 1000000
#define NGRAPHS 1000
#define EMBED 64
#define OUTDIM 128
#define NCONV 3
#define BN_EPS 1e-5f

#define SCAN_BLOCKS ((NNODES + 255) / 256)   // 391

typedef unsigned long long u64;

// ---------------- scratch (no allocs allowed) ----------------
// stats MUST be 16B-aligned (float4 loads) -> placed first.
struct alignas(16) ZBuf {     // zeroed via one cudaMemsetAsync each call
    float stats[NCONV * 2 * EMBED];   // offset 0, 1536 B (mult of 16)
    int   deg[NNODES];
    int   cnt;                 // scan arrival counter
    int   done;                // scan completion flag
};
__device__ ZBuf d_Z;

__device__ float d_h[NNODES * EMBED];      // node features
__device__ float d_t[NNODES * EMBED];      // agg + h (GEMM input)
__device__ float d_y[NNODES * EMBED];      // GEMM output (pre-BN)
__device__ int   d_rowptr[NNODES + 1];
__device__ int   d_cursor[NNODES];
__device__ float d_inv[NNODES];            // 1/max(deg,1)
__device__ int   d_aggr[512];
__device__ int   d_off[512];
__device__ unsigned d_edge[NEDGES];        // packed: (src << 8) | efeat
__device__ float d_gn[NGRAPHS * EMBED];

// ---------------- f32x2 helpers ----------------
__device__ __forceinline__ u64 ffma2(u64 a, u64 b, u64 c) {
    u64 d;
    asm("fma.rn.f32x2 %0, %1, %2, %3;" : "=l"(d) : "l"(a), "l"(b), "l"(c));
    return d;
}
__device__ __forceinline__ u64 pack2(float x) {
    u64 d;
    asm("mov.b64 %0, {%1, %1};" : "=l"(d) : "f"(x));
    return d;
}

// ---------------- setup kernels ----------------
__global__ void k_embed_count(const int* __restrict__ nfeat,
                              const float4* __restrict__ atom_embed,
                              const int* __restrict__ dst) {
    int i = blockIdx.x * 256 + threadIdx.x;
    if (i < NNODES * 16) {
        int n = i >> 4, c4 = i & 15;
        ((float4*)d_h)[i] = atom_embed[nfeat[n] * 16 + c4];
    }
    if (i < NEDGES) atomicAdd(&d_Z.deg[dst[i]], 1);
}

// single-kernel exclusive scan: block-local scan, last-arriving block computes
// the 391 block offsets, everyone else spins. 391 blocks all resident -> safe.
__global__ void k_scan() {
    __shared__ int s[256];
    __shared__ int s2[256];
    __shared__ int sdone;
    int t = threadIdx.x, bid = blockIdx.x;
    int i = bid * 256 + t;
    int v = (i < NNODES) ? d_Z.deg[i] : 0;
    s[t] = v;
    __syncthreads();
    #pragma unroll
    for (int off = 1; off < 256; off <<= 1) {
        int u = (t >= off) ? s[t - off] : 0;
        __syncthreads();
        s[t] += u;
        __syncthreads();
    }
    int lexcl = s[t] - v;
    int agg = s[255];
    if (t == 0) {
        d_aggr[bid] = agg;
        __threadfence();
        int old = atomicAdd(&d_Z.cnt, 1);
        sdone = (old == SCAN_BLOCKS - 1);
    }
    __syncthreads();
    if (sdone) {
        int a0 = (2 * t < SCAN_BLOCKS) ? d_aggr[2 * t] : 0;
        int a1 = (2 * t + 1 < SCAN_BLOCKS) ? d_aggr[2 * t + 1] : 0;
        s2[t] = a0 + a1;
        __syncthreads();
        #pragma unroll
        for (int off = 1; off < 256; off <<= 1) {
            int u = (t >= off) ? s2[t - off] : 0;
            __syncthreads();
            s2[t] += u;
            __syncthreads();
        }
        int ex = s2[t] - (a0 + a1);
        d_off[2 * t] = ex;
        d_off[2 * t + 1] = ex + a0;
        if (t == 255) d_rowptr[NNODES] = s2[255];
        __threadfence();
        if (t == 0) atomicExch(&d_Z.done, 1);
    }
    if (t == 0) {
        while (atomicAdd(&d_Z.done, 0) == 0) __nanosleep(40);
    }
    __syncthreads();
    int boff = __ldcg(&d_off[bid]);
    if (i < NNODES) {
        int r = lexcl + boff;
        d_rowptr[i] = r;
        d_cursor[i] = r;
        d_inv[i] = 1.f / (float)(v > 0 ? v : 1);
    }
}

__global__ void k_fill(const int* __restrict__ src,
                       const int* __restrict__ efeat,
                       const int* __restrict__ dst) {
    int e = blockIdx.x * blockDim.x + threadIdx.x;
    if (e >= NEDGES) return;
    int p = atomicAdd(&d_cursor[dst[e]], 1);
    d_edge[p] = ((unsigned)src[e] << 8) | (unsigned)efeat[e];
}

// ---------------- per-layer kernels ----------------
// warp per node, lane covers 2 channels (float2). 4x-unrolled edge loop with
// byte-offset packed edges. __launch_bounds__(256, 8) pins regs to 32 so all
// 8 blocks fit per SM (measured occupancy sweet spot).
// t[n] = mean_e relu(bond[ef] + h[src]) + h[n]
__global__ void __launch_bounds__(256, 8) k_msg(const float* __restrict__ bond) {
    __shared__ __align__(16) float bsh[5 * EMBED];
    int tid = threadIdx.x;
    for (int i = tid; i < 5 * EMBED; i += 256) bsh[i] = bond[i];
    __syncthreads();
    int warp = tid >> 5, lane = tid & 31;
    int node = blockIdx.x * 8 + warp;
    if (node >= NNODES) return;
    int rs = d_rowptr[node], re = d_rowptr[node + 1];
    const char* hb = (const char*)d_h + lane * 8;
    const char* bb = (const char*)bsh + lane * 8;
    float2 a0 = make_float2(0.f, 0.f), a1 = a0, a2 = a0, a3 = a0;
    int e = rs;
    for (; e + 3 < re; e += 4) {
        unsigned p0 = d_edge[e],     p1 = d_edge[e + 1];
        unsigned p2 = d_edge[e + 2], p3 = d_edge[e + 3];
        float2 h0 = *(const float2*)(hb + (p0 & 0xFFFFFF00u));
        float2 h1 = *(const float2*)(hb + (p1 & 0xFFFFFF00u));
        float2 h2 = *(const float2*)(hb + (p2 & 0xFFFFFF00u));
        float2 h3 = *(const float2*)(hb + (p3 & 0xFFFFFF00u));
        float2 b0 = *(const float2*)(bb + ((p0 & 255u) << 8));
        float2 b1 = *(const float2*)(bb + ((p1 & 255u) << 8));
        float2 b2 = *(const float2*)(bb + ((p2 & 255u) << 8));
        float2 b3 = *(const float2*)(bb + ((p3 & 255u) << 8));
        a0.x += fmaxf(b0.x + h0.x, 0.f);  a0.y += fmaxf(b0.y + h0.y, 0.f);
        a1.x += fmaxf(b1.x + h1.x, 0.f);  a1.y += fmaxf(b1.y + h1.y, 0.f);
        a2.x += fmaxf(b2.x + h2.x, 0.f);  a2.y += fmaxf(b2.y + h2.y, 0.f);
        a3.x += fmaxf(b3.x + h3.x, 0.f);  a3.y += fmaxf(b3.y + h3.y, 0.f);
    }
    for (; e < re; e++) {
        unsigned p0 = d_edge[e];
        float2 h0 = *(const float2*)(hb + (p0 & 0xFFFFFF00u));
        float2 b0 = *(const float2*)(bb + ((p0 & 255u) << 8));
        a0.x += fmaxf(b0.x + h0.x, 0.f);  a0.y += fmaxf(b0.y + h0.y, 0.f);
    }
    a0.x += a1.x + a2.x + a3.x;
    a0.y += a1.y + a2.y + a3.y;
    float inv = d_inv[node];
    float2 hn = ((const float2*)(d_h + (size_t)node * EMBED))[lane];
    float2 o;
    o.x = a0.x * inv + hn.x;
    o.y = a0.y * inv + hn.y;
    ((float2*)(d_t + (size_t)node * EMBED))[lane] = o;
}

// thread per node: y = t @ W + b (packed f32x2 FMA), then fused stats epilogue:
// each block reduces its OWN 256 just-written rows (L2-hot) into the global
// per-channel sum/sumsq accumulators. No separate stats kernel/pass.
__global__ void __launch_bounds__(256) k_gemm(const float* __restrict__ W,
                                              const float* __restrict__ b,
                                              int layer) {
    __shared__ ulonglong2 Ws[EMBED * 16];
    __shared__ float4 ssum[256], ssq[256];
    int tid = threadIdx.x;
    for (int i = tid; i < EMBED * 16; i += 256) Ws[i] = ((const ulonglong2*)W)[i];
    __syncthreads();
    int node = blockIdx.x * 256 + tid;
    if (node < NNODES) {
        u64 acc[32];
        const u64* bp = (const u64*)b;
        #pragma unroll
        for (int i = 0; i < 32; i++) acc[i] = bp[i];
        const float4* tp = (const float4*)(d_t + (size_t)node * EMBED);
        #pragma unroll 1
        for (int k4 = 0; k4 < 16; k4++) {
            float4 tv = tp[k4];
            #pragma unroll
            for (int j = 0; j < 4; j++) {
                float tk = (j == 0) ? tv.x : (j == 1) ? tv.y : (j == 2) ? tv.z : tv.w;
                u64 tkk = pack2(tk);
                int k = k4 * 4 + j;
                #pragma unroll
                for (int c8 = 0; c8 < 16; c8++) {
                    ulonglong2 w = Ws[k * 16 + c8];
                    acc[2 * c8]     = ffma2(tkk, w.x, acc[2 * c8]);
                    acc[2 * c8 + 1] = ffma2(tkk, w.y, acc[2 * c8 + 1]);
                }
            }
        }
        ulonglong2* yp = (ulonglong2*)(d_y + (size_t)node * EMBED);
        #pragma unroll
        for (int i = 0; i < 16; i++)
            yp[i] = make_ulonglong2(acc[2 * i], acc[2 * i + 1]);
    }
    __syncthreads();   // all y-rows of this block visible (cta-scope fence)
    // stats over this block's 256 rows
    int c4 = tid & 15, grp = tid >> 4;   // 16 row-groups x 16 float4-channels
    int base = blockIdx.x * 256;
    float4 sum = make_float4(0.f, 0.f, 0.f, 0.f), sq = sum;
    for (int r = grp; r < 256; r += 16) {
        int row = base + r;
        if (row >= NNODES) break;
        float4 v = ((const float4*)d_y)[row * 16 + c4];
        sum.x += v.x; sum.y += v.y; sum.z += v.z; sum.w += v.w;
        sq.x += v.x * v.x; sq.y += v.y * v.y; sq.z += v.z * v.z; sq.w += v.w * v.w;
    }
    ssum[tid] = sum; ssq[tid] = sq;
    __syncthreads();
    if (grp == 0) {
        #pragma unroll
        for (int g = 1; g < 16; g++) {
            float4 a = ssum[g * 16 + c4], q = ssq[g * 16 + c4];
            sum.x += a.x; sum.y += a.y; sum.z += a.z; sum.w += a.w;
            sq.x += q.x; sq.y += q.y; sq.z += q.z; sq.w += q.w;
        }
        float* st = d_Z.stats + layer * 128;
        atomicAdd(&st[c4 * 4 + 0], sum.x);
        atomicAdd(&st[c4 * 4 + 1], sum.y);
        atomicAdd(&st[c4 * 4 + 2], sum.z);
        atomicAdd(&st[c4 * 4 + 3], sum.w);
        atomicAdd(&st[64 + c4 * 4 + 0], sq.x);
        atomicAdd(&st[64 + c4 * 4 + 1], sq.y);
        atomicAdd(&st[64 + c4 * 4 + 2], sq.z);
        atomicAdd(&st[64 + c4 * 4 + 3], sq.w);
    }
}

// normalize + gamma/beta + optional relu + residual (h += act), float4 wide
__global__ void k_bn(int layer, const float* __restrict__ gamma,
                     const float* __restrict__ beta, int do_relu) {
    int i = blockIdx.x * blockDim.x + threadIdx.x;   // float4 index
    if (i >= NNODES * 16) return;
    int c4 = i & 15;
    const float* st = d_Z.stats + layer * 128;
    const float invN = 1.f / (float)NNODES;
    float4 s1 = ((const float4*)st)[c4];
    float4 s2 = ((const float4*)(st + 64))[c4];
    float4 g  = ((const float4*)gamma)[c4];
    float4 be = ((const float4*)beta)[c4];
    float4 y  = ((const float4*)d_y)[i];
    float4 h  = ((const float4*)d_h)[i];
    float mu, var, rs, v;
    #define BN1(X) \
        mu = s1.X * invN; var = s2.X * invN - mu * mu; \
        rs = rsqrtf(fmaxf(var, 0.f) + BN_EPS); \
        v = (y.X - mu) * rs * g.X + be.X; \
        if (do_relu) v = fmaxf(v, 0.f); \
        h.X += v;
    BN1(x) BN1(y) BN1(z) BN1(w)
    #undef BN1
    ((float4*)d_h)[i] = h;
}

// ---------------- tail kernel: pool + pred fused ----------------
// block per graph: mean over the graph's node range (binary search on sorted
// gids), then the first OUTDIM threads compute out[g] = mean @ pred_W + pred_b.
__global__ void k_poolpred(const int* __restrict__ gids,
                           const float* __restrict__ W,
                           const float* __restrict__ b,
                           float* __restrict__ out) {
    __shared__ float red[256];
    __shared__ float gs[EMBED];
    __shared__ int range[2];
    int g = blockIdx.x, tid = threadIdx.x;
    int c = tid & 63, grp = tid >> 6;
    if (tid < 2) {
        int target = g + tid;
        int lo = 0, hi = NNODES;
        while (lo < hi) { int m = (lo + hi) >> 1; if (gids[m] < target) lo = m + 1; else hi = m; }
        range[tid] = lo;
    }
    __syncthreads();
    int start = range[0], end = range[1];
    float acc = 0.f;
    for (int n = start + grp; n < end; n += 4)
        acc += d_h[(size_t)n * EMBED + c];
    red[tid] = acc;
    __syncthreads();
    if (grp == 0) {
        float s = red[c] + red[64 + c] + red[128 + c] + red[192 + c];
        int cntg = end - start;
        gs[c] = s / (float)(cntg > 0 ? cntg : 1);
    }
    __syncthreads();
    if (tid < OUTDIM) {
        float a = b[tid];
        #pragma unroll
        for (int k = 0; k < EMBED; k++) a += gs[k] * W[k * OUTDIM + tid];
        out[g * OUTDIM + tid] = a;
    }
}

// ---------------- launch ----------------
extern "C" void kernel_launch(void* const* d_in, const int* in_sizes, int n_in,
                              void* d_out, int out_size) {
    const int*   nfeat      = (const int*)d_in[0];
    const int*   efeat      = (const int*)d_in[1];
    const int*   src        = (const int*)d_in[2];
    const int*   dst        = (const int*)d_in[3];
    const int*   gids       = (const int*)d_in[4];
    const float* atom_embed = (const float*)d_in[5];
    const float* bond_embed = (const float*)d_in[6];
    const float* conv_W     = (const float*)d_in[7];
    const float* conv_b     = (const float*)d_in[8];
    const float* bn_gamma   = (const float*)d_in[9];
    const float* bn_beta    = (const float*)d_in[10];
    const float* pred_W     = (const float*)d_in[11];
    const float* pred_b     = (const float*)d_in[12];
    float* out = (float*)d_out;

    void* zp = nullptr;
    cudaGetSymbolAddress(&zp, d_Z);
    cudaMemsetAsync(zp, 0, sizeof(ZBuf), 0);

    k_embed_count<<<(NNODES * 16 + 255) / 256, 256>>>(nfeat, (const float4*)atom_embed, dst);
    k_scan<<<SCAN_BLOCKS, 256>>>();
    k_fill<<<(NEDGES + 255) / 256, 256>>>(src, efeat, dst);

    for (int i = 0; i < NCONV; i++) {
        k_msg<<<(NNODES + 7) / 8, 256>>>(bond_embed + i * 5 * EMBED);
        k_gemm<<<(NNODES + 255) / 256, 256>>>(conv_W + i * EMBED * EMBED,
                                              conv_b + i * EMBED, i);
        k_bn<<<(NNODES * 16 + 255) / 256, 256>>>(i, bn_gamma + i * EMBED,
                                                 bn_beta + i * EMBED,
                                                 (i < NCONV - 1) ? 1 : 0);
    }

    k_poolpred<<<NGRAPHS, 256>>>(gids, pred_W, pred_b, out);
}